// round 15
// baseline (speedup 1.0000x reference)
#include <cuda_runtime.h>
#include <cuda_bf16.h>
#include <math.h>

// Problem constants: M=4096, K=1024, E=8, N=1024, TOPK=2
#define M_ROWS   4096
#define K_DIM    1024
#define N_DIM    1024
#define N2_DIM   2048
#define E_NUM    8
#define TOPK     2
#define T_TASKS  (M_ROWS * TOPK)          // 8192
#define P_CAP    (T_TASKS + E_NUM * 128)  // 9216 padded task positions
#define NT_TILES (P_CAP / 128)            // 72 row-tiles of 128

// ---------------- device scratch (static, no runtime allocation) -------------
__device__ int   g_task_row[P_CAP];                 // source row per position (-1 = pad)
__device__ float g_task_coef[P_CAP];                // routing weight per position
__device__ int   g_tile_expert[NT_TILES];           // expert id per 128-row tile (-1 = empty)
__device__ float g_hbuf[(size_t)P_CAP * N_DIM];     // intermediate h = silu(gate)*up

// ---------------- packed f32x2 helpers (Blackwell FFMA2 path) ----------------
__device__ __forceinline__ unsigned long long fma2(unsigned long long a,
                                                   unsigned long long b,
                                                   unsigned long long c) {
    unsigned long long d;
    asm("fma.rn.f32x2 %0, %1, %2, %3;" : "=l"(d) : "l"(a), "l"(b), "l"(c));
    return d;
}
__device__ __forceinline__ unsigned long long pack2(float x) {
    unsigned long long d;
    unsigned int xi = __float_as_uint(x);
    asm("mov.b64 %0, {%1, %1};" : "=l"(d) : "r"(xi));
    return d;
}
__device__ __forceinline__ void unpack2(unsigned long long v, float& lo, float& hi) {
    unsigned int a, b;
    asm("mov.b64 {%0, %1}, %2;" : "=r"(a), "=r"(b) : "l"(v));
    lo = __uint_as_float(a);
    hi = __uint_as_float(b);
}

__device__ __forceinline__ float silu_f(float g) {
    // g * sigmoid(g); expf(-g) -> inf for very negative g gives g/inf = -0 (correct limit)
    return g / (1.0f + expf(-g));
}

// ---------------- kernel 0: zero output --------------------------------------
__global__ void k_zero(float* __restrict__ out) {
    size_t i = (size_t)blockIdx.x * blockDim.x + threadIdx.x;
    ((float4*)out)[i] = make_float4(0.f, 0.f, 0.f, 0.f);
}

// ---------------- kernel 1: routing / counting-sort by expert ----------------
// candA / candB are the two 8192-element inputs (topk_weights fp32, topk_ids
// int32 or int64, order unknown). Identify ids by value-range sniffing:
// valid ids are in [0,8) under the correct width; U(0,1) float bit patterns
// are >= ~1e9 as ints. All detection reads stay within 32KB (safe for both
// widths: 8192 int32 = 32KB, and we read only 4096 int64 words = 32KB).
__global__ void k_sched(const void* __restrict__ candA,
                        const void* __restrict__ candB) {
    __shared__ int cnt[E_NUM];
    __shared__ int cur[E_NUM];
    __shared__ int bad64[2], bad32[2];
    const int tid = threadIdx.x;

    if (tid < 2) { bad64[tid] = 0; bad32[tid] = 0; }
    if (tid < E_NUM) cnt[tid] = 0;
    for (int p = tid; p < P_CAP; p += 256) { g_task_row[p] = -1; g_task_coef[p] = 0.f; }
    for (int i = tid; i < NT_TILES; i += 256) g_tile_expert[i] = -1;
    __syncthreads();

    // --- dtype / identity detection ---
    const void* cands[2] = { candA, candB };
#pragma unroll
    for (int c = 0; c < 2; c++) {
        const long long* p64 = (const long long*)cands[c];
        const int*       p32 = (const int*)cands[c];
        int b64 = 0, b32 = 0;
        for (int t = tid; t < T_TASKS / 2; t += 256) {      // 4096 x int64 = 32KB
            long long v = p64[t];
            if (v < 0 || v >= E_NUM) b64 = 1;
        }
        for (int t = tid; t < T_TASKS; t += 256) {          // 8192 x int32 = 32KB
            int v = p32[t];
            if (v < 0 || v >= E_NUM) b32 = 1;
        }
        if (b64) atomicOr(&bad64[c], 1);
        if (b32) atomicOr(&bad32[c], 1);
    }
    __syncthreads();

    // pick ids candidate: the one that parses in-range under some width.
    // (int64 data also passes the int32 test — even words = value, odd = 0 —
    //  so prefer the int64 interpretation when its test passes.)
    int ids_idx  = (!bad64[0] || !bad32[0]) ? 0 : 1;
    int mode64   = !bad64[ids_idx];
    const long long* ids64 = (const long long*)cands[ids_idx];
    const int*       ids32 = (const int*)cands[ids_idx];
    const float*     wts   = (const float*)cands[1 - ids_idx];

    // --- count tasks per expert ---
    for (int t = tid; t < T_TASKS; t += 256) {
        int e = mode64 ? (int)ids64[t] : ids32[t];
        e = min(max(e, 0), E_NUM - 1);
        atomicAdd(&cnt[e], 1);
    }
    __syncthreads();

    if (tid == 0) {
        int off = 0;
        for (int e = 0; e < E_NUM; e++) {
            cur[e] = off;
            int nt = (cnt[e] + 127) >> 7;           // 128-padded tiles
            for (int i = 0; i < nt; i++) g_tile_expert[(off >> 7) + i] = e;
            off += nt << 7;
        }
    }
    __syncthreads();

    for (int t = tid; t < T_TASKS; t += 256) {
        int e = mode64 ? (int)ids64[t] : ids32[t];
        e = min(max(e, 0), E_NUM - 1);
        int p = atomicAdd(&cur[e], 1);
        g_task_row[p]  = t >> 1;        // t = row*TOPK + slot
        g_task_coef[p] = wts[t];
    }
}

// ---------------- kernel 2: GEMM1 + SiLU*up ----------------------------------
// h[p, n] = silu( sum_k x[row(p),k]*w1[e,k,n] ) * ( sum_k x[row(p),k]*w1[e,k,n+N] )
// tile: 128 rows x 64 gate-cols (+64 up-cols), BK=16, 256 threads, 8x(4+4) micro
__global__ __launch_bounds__(256, 2) void k_gemm1(const float* __restrict__ x,
                                                  const float* __restrict__ w1) {
    const int tile = blockIdx.y;
    const int e = g_tile_expert[tile];
    if (e < 0) return;
    const int n0 = blockIdx.x * 64;
    const int p0 = tile * 128;

    __shared__ float As[16][132];   // [k][m], padded stride (conflict-free)
    __shared__ float Wg[16][64];
    __shared__ float Wu[16][64];

    const int tid = threadIdx.x;

    int mA[2], k4A[2];
    const float* aPtr[2];
#pragma unroll
    for (int i = 0; i < 2; i++) {
        int idx = tid + i * 256;          // 0..511
        mA[i]  = idx >> 2;                // 0..127
        k4A[i] = idx & 3;                 // float4 index within BK=16
        int row = g_task_row[p0 + mA[i]];
        aPtr[i] = (row >= 0) ? (x + (size_t)row * K_DIM + k4A[i] * 4) : nullptr;
    }

    const int kw = tid >> 4;              // 0..15
    const int nf = (tid & 15) * 4;        // 0..60
    const float* gPtr = w1 + (size_t)e * K_DIM * N2_DIM + (size_t)kw * N2_DIM + n0 + nf;
    const float* uPtr = gPtr + N_DIM;

    const int ty = tid >> 4;              // row group (8 rows)
    const int tx = tid & 15;              // col group (4 cols)

    unsigned long long ag[8][2], au[8][2];
#pragma unroll
    for (int r = 0; r < 8; r++) {
        ag[r][0] = 0ull; ag[r][1] = 0ull;
        au[r][0] = 0ull; au[r][1] = 0ull;
    }

    for (int kt = 0; kt < K_DIM / 16; kt++) {
        const int k0 = kt * 16;
        float4 av[2];
#pragma unroll
        for (int i = 0; i < 2; i++)
            av[i] = aPtr[i] ? *(const float4*)(aPtr[i] + k0)
                            : make_float4(0.f, 0.f, 0.f, 0.f);
        float4 gv = *(const float4*)(gPtr + (size_t)k0 * N2_DIM);
        float4 uv = *(const float4*)(uPtr + (size_t)k0 * N2_DIM);

        __syncthreads();   // previous tile fully consumed
#pragma unroll
        for (int i = 0; i < 2; i++) {
            As[k4A[i] * 4 + 0][mA[i]] = av[i].x;
            As[k4A[i] * 4 + 1][mA[i]] = av[i].y;
            As[k4A[i] * 4 + 2][mA[i]] = av[i].z;
            As[k4A[i] * 4 + 3][mA[i]] = av[i].w;
        }
        *(float4*)&Wg[kw][nf] = gv;
        *(float4*)&Wu[kw][nf] = uv;
        __syncthreads();

#pragma unroll
        for (int kk = 0; kk < 16; kk++) {
            float4 a0 = *(const float4*)&As[kk][ty * 8];
            float4 a1 = *(const float4*)&As[kk][ty * 8 + 4];
            ulonglong2 bg = *(const ulonglong2*)&Wg[kk][tx * 4];
            ulonglong2 bu = *(const ulonglong2*)&Wu[kk][tx * 4];
            unsigned long long ap[8];
            ap[0] = pack2(a0.x); ap[1] = pack2(a0.y);
            ap[2] = pack2(a0.z); ap[3] = pack2(a0.w);
            ap[4] = pack2(a1.x); ap[5] = pack2(a1.y);
            ap[6] = pack2(a1.z); ap[7] = pack2(a1.w);
#pragma unroll
            for (int r = 0; r < 8; r++) {
                ag[r][0] = fma2(ap[r], bg.x, ag[r][0]);
                ag[r][1] = fma2(ap[r], bg.y, ag[r][1]);
                au[r][0] = fma2(ap[r], bu.x, au[r][0]);
                au[r][1] = fma2(ap[r], bu.y, au[r][1]);
            }
        }
    }

    // epilogue: silu(gate)*up -> hbuf (pad rows: A=0 -> silu(0)*0 = 0, safe)
    const int pbase = p0 + ty * 8;
#pragma unroll
    for (int r = 0; r < 8; r++) {
        float g0, g1, g2, g3, u0, u1, u2, u3;
        unpack2(ag[r][0], g0, g1); unpack2(ag[r][1], g2, g3);
        unpack2(au[r][0], u0, u1); unpack2(au[r][1], u2, u3);
        float4 hv;
        hv.x = silu_f(g0) * u0;
        hv.y = silu_f(g1) * u1;
        hv.z = silu_f(g2) * u2;
        hv.w = silu_f(g3) * u3;
        *(float4*)(g_hbuf + (size_t)(pbase + r) * N_DIM + n0 + tx * 4) = hv;
    }
}

// ---------------- kernel 3: GEMM2 + scale + scatter-add ----------------------
// out[row(p), c] += coef(p) * sum_j h[p,j] * w2[e,j,c]
__global__ __launch_bounds__(256, 2) void k_gemm2(const float* __restrict__ w2,
                                                  float* __restrict__ out) {
    const int tile = blockIdx.y;
    const int e = g_tile_expert[tile];
    if (e < 0) return;
    const int c0 = blockIdx.x * 64;
    const int p0 = tile * 128;

    __shared__ float As[16][132];
    __shared__ float Wb[16][64];

    const int tid = threadIdx.x;

    int mA[2], k4A[2];
#pragma unroll
    for (int i = 0; i < 2; i++) {
        int idx = tid + i * 256;
        mA[i]  = idx >> 2;
        k4A[i] = idx & 3;
    }

    const int kw = tid >> 4;
    const int nf = (tid & 15) * 4;
    const float* bPtr = w2 + (size_t)e * N_DIM * K_DIM + (size_t)kw * K_DIM + c0 + nf;

    const int ty = tid >> 4;
    const int tx = tid & 15;

    unsigned long long ac[8][2];
#pragma unroll
    for (int r = 0; r < 8; r++) { ac[r][0] = 0ull; ac[r][1] = 0ull; }

    for (int kt = 0; kt < N_DIM / 16; kt++) {
        const int k0 = kt * 16;
        float4 av[2];
#pragma unroll
        for (int i = 0; i < 2; i++)
            av[i] = *(const float4*)(g_hbuf + (size_t)(p0 + mA[i]) * N_DIM + k0 + k4A[i] * 4);
        float4 bv = *(const float4*)(bPtr + (size_t)k0 * K_DIM);

        __syncthreads();
#pragma unroll
        for (int i = 0; i < 2; i++) {
            As[k4A[i] * 4 + 0][mA[i]] = av[i].x;
            As[k4A[i] * 4 + 1][mA[i]] = av[i].y;
            As[k4A[i] * 4 + 2][mA[i]] = av[i].z;
            As[k4A[i] * 4 + 3][mA[i]] = av[i].w;
        }
        *(float4*)&Wb[kw][nf] = bv;
        __syncthreads();

#pragma unroll
        for (int kk = 0; kk < 16; kk++) {
            float4 a0 = *(const float4*)&As[kk][ty * 8];
            float4 a1 = *(const float4*)&As[kk][ty * 8 + 4];
            ulonglong2 bb = *(const ulonglong2*)&Wb[kk][tx * 4];
            unsigned long long ap[8];
            ap[0] = pack2(a0.x); ap[1] = pack2(a0.y);
            ap[2] = pack2(a0.z); ap[3] = pack2(a0.w);
            ap[4] = pack2(a1.x); ap[5] = pack2(a1.y);
            ap[6] = pack2(a1.z); ap[7] = pack2(a1.w);
#pragma unroll
            for (int r = 0; r < 8; r++) {
                ac[r][0] = fma2(ap[r], bb.x, ac[r][0]);
                ac[r][1] = fma2(ap[r], bb.y, ac[r][1]);
            }
        }
    }

    // epilogue: scale by routing coef, scatter-add to output. Exactly two
    // commutative fp32 adds per element onto a zeroed buffer -> deterministic.
#pragma unroll
    for (int r = 0; r < 8; r++) {
        const int p = p0 + ty * 8 + r;
        const int row = g_task_row[p];
        if (row < 0) continue;
        const float coef = g_task_coef[p];
        float v0, v1, v2, v3;
        unpack2(ac[r][0], v0, v1);
        unpack2(ac[r][1], v2, v3);
        float* o = out + (size_t)row * K_DIM + c0 + tx * 4;
        atomicAdd(o + 0, coef * v0);
        atomicAdd(o + 1, coef * v1);
        atomicAdd(o + 2, coef * v2);
        atomicAdd(o + 3, coef * v3);
    }
}

// ---------------- launch ------------------------------------------------------
extern "C" void kernel_launch(void* const* d_in, const int* in_sizes, int n_in,
                              void* d_out, int out_size) {
    // Identify inputs by element count (order-robust):
    //   hidden_states: 4096*1024   = 4194304
    //   w1:            8*1024*2048 = 16777216
    //   w2:            8*1024*1024 = 8388608
    //   topk_weights / topk_ids: both 8192 (disambiguated on-device)
    int ix = -1, iw1 = -1, iw2 = -1, ia = -1, ib = -1;
    for (int i = 0; i < n_in; i++) {
        if      (in_sizes[i] == 16777216) iw1 = i;
        else if (in_sizes[i] == 8388608)  iw2 = i;
        else if (in_sizes[i] == 4194304)  ix  = i;
        else if (in_sizes[i] == 8192)     { if (ia < 0) ia = i; else ib = i; }
    }
    const float* x   = (const float*)d_in[ix];
    const float* w1  = (const float*)d_in[iw1];
    const float* w2  = (const float*)d_in[iw2];
    float* out = (float*)d_out;

    k_zero<<<(M_ROWS * K_DIM) / (256 * 4), 256>>>(out);
    k_sched<<<1, 256>>>(d_in[ia], d_in[ib]);

    dim3 grid1(N_DIM / 64, NT_TILES);   // 16 x 72
    k_gemm1<<<grid1, 256>>>(x, w1);

    dim3 grid2(K_DIM / 64, NT_TILES);   // 16 x 72
    k_gemm2<<<grid2, 256>>>(w2, out);
}